// round 13
// baseline (speedup 1.0000x reference)
#include <cuda_runtime.h>
#include <math.h>

#define IN_DIM 768
#define KSEL   38
#define NF     76
#define NFP    80
#define NC1    96     // phase-1 output cols padded (3 per lane x 32)
#define HID    256
#define ROWS   64
#define THREADS 512
#define KFOLD  384

// strides (floats)
#define SR   68       // col-major [.][row] buffers (HT, ZS)
#define XR   96       // XIN row-major stride
#define XSR  68       // XS row-major stride
#define BSR  68       // BS [c][k] stride (≡4 mod 32: conflict-free 4-phase LDS.128)
#define W1R  84       // W1 [c][k] stride (≡20 mod 32: conflict-free 4-phase LDS.128)
#define W2S  84       // W2 [k][o] stride (GEMM2, unchanged)
#define CSS  132      // C tile stride (phase3, unchanged)

// smem layout (float offsets)
#define OFF_XIN 0                       // [64][96] = 6144 (row-major)
#define OFF_W   6144                    // 21504-float aliased region
#define OFF_XS  OFF_W                   //   [64][68] = 4352
#define OFF_BS  (OFF_W + 4352)          //   [96][68] = 6528
#define OFF_CS  OFF_W                   //   [76][132] = 10032
#define OFF_HT  (OFF_W + 21504)         // [256][68] = 17408 (col-major)
#define OFF_ZS  (OFF_HT + 17408)        // [76][68]  = 5168 (col-major)
#define OFF_LNS (OFF_ZS + 5168)         // [64][4]
#define SMEM_FLOATS (OFF_LNS + 256)     // 50480
#define SMEM_BYTES  (SMEM_FLOATS * 4)   // 201920 B

typedef unsigned long long u64;

__device__ __forceinline__ void ffma2(u64& d, u64 a, u64 b) {
    asm("fma.rn.f32x2 %0, %1, %2, %0;" : "+l"(d) : "l"(a), "l"(b));
}
__device__ __forceinline__ u64 bcast2(float a) {
    u64 r;
    asm("mov.b64 %0, {%1, %1};" : "=l"(r) : "f"(a));
    return r;
}
__device__ __forceinline__ float2 unpack2(u64 v) {
    float2 r;
    asm("mov.b64 {%0, %1}, %2;" : "=f"(r.x), "=f"(r.y) : "l"(v));
    return r;
}
// k-paired quad FMA: acc.(lo,hi) += a.(k0,k1)*b.(k0,k1) + a.(k2,k3)*b.(k2,k3)
__device__ __forceinline__ void ffma2q(u64& d, const float4& a, const float4& b) {
    const u64* ap = reinterpret_cast<const u64*>(&a);
    const u64* bp = reinterpret_cast<const u64*>(&b);
    ffma2(d, ap[0], bp[0]);
    ffma2(d, ap[1], bp[1]);
}
__device__ __forceinline__ float hadd2(u64 v) {
    float2 f = unpack2(v);
    return f.x + f.y;
}

// Precomputed tables
__device__ float g_B2T[NC1 * KFOLD];    // folded analysis, col-major [c][k]; rows c>=76 zero
__device__ float g_W1P[2][HID * W1R];   // [p][c][k] = w1[c][k], k padded 76->84
__device__ float g_W2T[2][HID * NFP];   // [p][k][o] = w2[o][k], o padded 0
__device__ float g_C2[NF * KFOLD];      // folded synthesis [k][n]

__global__ void precompute_all(const int* __restrict__ indices,
                               const float* __restrict__ mu_w1, const float* __restrict__ sg_w1,
                               const float* __restrict__ mu_w2, const float* __restrict__ sg_w2) {
    int t = blockIdx.x * blockDim.x + threadIdx.x;
    if (t < NC1 * KFOLD) {
        int c = t / KFOLD, kk = t - c * KFOLD;
        if (c >= NF) { g_B2T[t] = 0.f; return; }
        int f = indices[(c < KSEL) ? c : (c - KSEL)];
        int m = (kk < 192) ? kk : kk - 192;
        int mm = (f * m) % IN_DIM;
        float s, cs;
        sincospif((float)mm * (1.0f / 384.0f), &s, &cs);
        float v;
        if (kk < 192) v = (c < KSEL) ? cs : -s;
        else          v = (c < KSEL) ? -s : -cs;
        g_B2T[t] = v;
        return;
    }
    t -= NC1 * KFOLD;
    const int N1 = HID * W1R;
    if (t < 2 * N1) {
        int p = t / N1, r = t - p * N1;
        int j = r / W1R, i = r - j * W1R;
        const float* w1 = p ? sg_w1 : mu_w1;
        g_W1P[p][r] = (i < NF) ? w1[j * NF + i] : 0.f;
        return;
    }
    t -= 2 * N1;
    const int N2 = HID * NFP;
    if (t < 2 * N2) {
        int p = t / N2, r = t - p * N2;
        int k = r / NFP, c = r - k * NFP;
        const float* w2 = p ? sg_w2 : mu_w2;
        g_W2T[p][r] = (c < NF) ? w2[c * HID + k] : 0.f;
        return;
    }
    t -= 2 * N2;
    if (t < NF * KFOLD) {
        int k = t / KFOLD, cc = t - k * KFOLD;
        int f = indices[(k < KSEL) ? k : (k - KSEL)];
        int m = (cc < 192) ? cc : cc - 192;
        int mm = (f * m) % IN_DIM;
        float s, cs;
        sincospif((float)mm * (1.0f / 384.0f), &s, &cs);
        float wq = (f == 0 || 2 * f == IN_DIM) ? (1.0f / IN_DIM) : (2.0f / IN_DIM);
        float v;
        if (cc < 192) v = (k < KSEL) ? (wq * cs) : (-wq * s);
        else          v = (k < KSEL) ? (wq * s) : (wq * cs);
        g_C2[t] = v;
    }
}

__global__ __launch_bounds__(THREADS, 1)
void fused_kernel(const float* __restrict__ x,
                  const float* __restrict__ eps,
                  const float* __restrict__ mu_b1, const float* __restrict__ mu_g,
                  const float* __restrict__ mu_beta, const float* __restrict__ mu_b2,
                  const float* __restrict__ sg_b1, const float* __restrict__ sg_g,
                  const float* __restrict__ sg_beta, const float* __restrict__ sg_b2,
                  float* __restrict__ out)
{
    extern __shared__ float sm[];
    float* XIN = sm + OFF_XIN;
    float* WB  = sm + OFF_W;
    float* XS  = sm + OFF_XS;
    float* BS  = sm + OFF_BS;
    float* CS  = sm + OFF_CS;
    float* HT  = sm + OFF_HT;
    float* ZS  = sm + OFF_ZS;
    float* LNS = sm + OFF_LNS;

    const int tid  = threadIdx.x;
    const int w    = tid >> 5;
    const int lane = tid & 31;
    const int tc16 = lane & 15;
    const int s    = lane >> 4;
    const int r4   = w * 4;           // GEMM2 row base (16 warps x 4 rows)
    const int rg   = w & 7;
    const int ch   = w >> 3;
    const int r8   = rg * 8;          // GEMM1/phase3 row base
    const int row0 = blockIdx.x * ROWS;

    // ===== Phase 1: XIN[64][96] = fold(x) @ B2T  (k-paired FFMA2, no split-k) =====
    u64 acc1[4][3];
    #pragma unroll
    for (int r = 0; r < 4; r++)
        #pragma unroll
        for (int m = 0; m < 3; m++) acc1[r][m] = 0;

    for (int kb = 0; kb < KFOLD; kb += 64) {
        __syncthreads();
        {   // stage folded x row-major (native layout, float4 in/out)
            int r = tid & 63, cc = (tid >> 6) * 8;
            const float* xp = &x[(size_t)(row0 + r) * IN_DIM + kb + cc];
            float4 v0 = *reinterpret_cast<const float4*>(xp);
            float4 v1 = *reinterpret_cast<const float4*>(xp + 4);
            float4 q0 = *reinterpret_cast<const float4*>(xp + 384);
            float4 q1 = *reinterpret_cast<const float4*>(xp + 388);
            *reinterpret_cast<float4*>(&XS[r * XSR + cc]) =
                make_float4(v0.x - q0.x, v0.y - q0.y, v0.z - q0.z, v0.w - q0.w);
            *reinterpret_cast<float4*>(&XS[r * XSR + cc + 4]) =
                make_float4(v1.x - q1.x, v1.y - q1.y, v1.z - q1.z, v1.w - q1.w);
        }
        for (int idx = tid; idx < NC1 * 16; idx += THREADS) {
            int c = idx >> 4, k4 = (idx & 15) * 4;
            *reinterpret_cast<float4*>(&BS[c * BSR + k4]) =
                *reinterpret_cast<const float4*>(&g_B2T[c * KFOLD + kb + k4]);
        }
        __syncthreads();
        #pragma unroll 2
        for (int kt = 0; kt < 16; kt++) {
            int kk = kt * 4;
            float4 b0 = *reinterpret_cast<const float4*>(&BS[lane * BSR + kk]);
            float4 b1v = *reinterpret_cast<const float4*>(&BS[(lane + 32) * BSR + kk]);
            float4 b2v = *reinterpret_cast<const float4*>(&BS[(lane + 64) * BSR + kk]);
            #pragma unroll
            for (int r = 0; r < 4; r++) {
                float4 a = *reinterpret_cast<const float4*>(&XS[(r4 + r) * XSR + kk]);
                ffma2q(acc1[r][0], a, b0);
                ffma2q(acc1[r][1], a, b1v);
                ffma2q(acc1[r][2], a, b2v);
            }
        }
    }
    #pragma unroll
    for (int r = 0; r < 4; r++)
        #pragma unroll
        for (int m = 0; m < 3; m++)
            XIN[(r4 + r) * XR + lane + 32 * m] = hadd2(acc1[r][m]);

    // ===== Phase 2: two MLPs =====
    float zmu[4][5];
    #pragma unroll 1
    for (int p = 0; p < 2; p++) {
        const float* b1 = p ? sg_b1 : mu_b1;
        const float* gp = p ? sg_g : mu_g;
        const float* bp = p ? sg_beta : mu_beta;
        const float* b2 = p ? sg_b2 : mu_b2;
        const float* w1p = g_W1P[p];
        const float* w2t = g_W2T[p];

        __syncthreads();   // XIN ready (p=0) / WB free
        for (int idx = tid; idx < HID * 21; idx += THREADS) {
            int c = idx / 21, k4 = (idx - c * 21) * 4;
            *reinterpret_cast<float4*>(&WB[c * W1R + k4]) =
                *reinterpret_cast<const float4*>(&w1p[c * W1R + k4]);
        }
        __syncthreads();

        // GEMM1: H[64][256] = XIN @ W1 — 8-row x 4-strided-col tiles, full-k
        const int cb = ch * 128 + lane;   // cols cb + 32*m
        float bb[4];
        #pragma unroll
        for (int m = 0; m < 4; m++) bb[m] = __ldg(&b1[cb + 32 * m]);

        u64 acc[8][4];
        #pragma unroll
        for (int r = 0; r < 8; r++)
            #pragma unroll
            for (int m = 0; m < 4; m++) acc[r][m] = 0;
        #pragma unroll 1
        for (int kt = 0; kt < 19; kt++) {
            int kk = kt * 4;
            float4 bm0 = *reinterpret_cast<const float4*>(&WB[(cb +  0) * W1R + kk]);
            float4 bm1 = *reinterpret_cast<const float4*>(&WB[(cb + 32) * W1R + kk]);
            float4 bm2 = *reinterpret_cast<const float4*>(&WB[(cb + 64) * W1R + kk]);
            float4 bm3 = *reinterpret_cast<const float4*>(&WB[(cb + 96) * W1R + kk]);
            #pragma unroll
            for (int r = 0; r < 8; r++) {
                float4 a = *reinterpret_cast<const float4*>(&XIN[(r8 + r) * XR + kk]);
                ffma2q(acc[r][0], a, bm0);
                ffma2q(acc[r][1], a, bm1);
                ffma2q(acc[r][2], a, bm2);
                ffma2q(acc[r][3], a, bm3);
            }
        }
        float af[8][4];
        {
            float sv[8], sq[8];
            #pragma unroll
            for (int r = 0; r < 8; r++) {
                sv[r] = 0.f; sq[r] = 0.f;
                #pragma unroll
                for (int m = 0; m < 4; m++) {
                    float v = hadd2(acc[r][m]) + bb[m];
                    af[r][m] = v;
                    sv[r] += v;
                    sq[r] = fmaf(v, v, sq[r]);
                }
            }
            #pragma unroll
            for (int o = 1; o <= 16; o <<= 1) {
                #pragma unroll
                for (int r = 0; r < 8; r++) {
                    sv[r] += __shfl_xor_sync(0xffffffffu, sv[r], o);
                    sq[r] += __shfl_xor_sync(0xffffffffu, sq[r], o);
                }
            }
            if (lane == 0) {
                #pragma unroll
                for (int r = 0; r < 8; r++)
                    *reinterpret_cast<float2*>(&LNS[(r8 + r) * 4 + ch * 2]) =
                        make_float2(sv[r], sq[r]);
            }
        }
        __syncthreads();   // LNS ready; all GEMM1 WB reads done

        // stage W2 now (overlaps with LN/GELU below)
        for (int idx = tid; idx < HID * 20; idx += THREADS) {
            int k = idx / 20, c4 = (idx - k * 20) * 4;
            *reinterpret_cast<float4*>(&WB[k * W2S + c4]) =
                *reinterpret_cast<const float4*>(&w2t[k * NFP + c4]);
        }
        {
            float gg[4], bt[4];
            #pragma unroll
            for (int m = 0; m < 4; m++) {
                gg[m] = __ldg(&gp[cb + 32 * m]);
                bt[m] = __ldg(&bp[cb + 32 * m]);
            }
            #pragma unroll
            for (int r = 0; r < 8; r++) {
                float4 st = *reinterpret_cast<const float4*>(&LNS[(r8 + r) * 4]);
                float mean = (st.x + st.z) * (1.f / HID);
                float inv  = rsqrtf((st.y + st.w) * (1.f / HID) - mean * mean + 1e-5f);
                #pragma unroll
                for (int m = 0; m < 4; m++) {
                    float hn = (af[r][m] - mean) * inv * gg[m] + bt[m];
                    af[r][m] = 0.5f * hn * (1.f + erff(hn * 0.70710678118654752f));
                }
            }
        }
        #pragma unroll
        for (int m = 0; m < 4; m++) {
            int c = cb + 32 * m;
            *reinterpret_cast<float4*>(&HT[c * SR + r8]) =
                make_float4(af[0][m], af[1][m], af[2][m], af[3][m]);
            *reinterpret_cast<float4*>(&HT[c * SR + r8 + 4]) =
                make_float4(af[4][m], af[5][m], af[6][m], af[7][m]);
        }
        __syncthreads();   // HT + W2 ready

        // eps prefetch (consumed in p==1 epilogue)
        float4 ev[4]; float e4[4];
        if (p == 1) {
            #pragma unroll
            for (int j = 0; j < 4; j++) {
                int row = row0 + r4 + j;
                ev[j] = __ldg(reinterpret_cast<const float4*>(&eps[(size_t)row * NF + tc16 * 4]));
                e4[j] = (tc16 < 12) ? __ldg(&eps[(size_t)row * NF + 64 + tc16]) : 0.f;
            }
        }

        // GEMM2: Z[64][80] = gelu(H) @ W2^T (split-k by s, col-paired FFMA2)
        u64 acc2p[4][2];
        float acc2s[4];
        #pragma unroll
        for (int j = 0; j < 4; j++) { acc2p[j][0] = 0; acc2p[j][1] = 0; acc2s[j] = 0.f; }
        const int kbase = s * 128;
        #pragma unroll 4
        for (int kt = 0; kt < 128; kt++) {
            int k = kbase + kt;
            float4 av = *reinterpret_cast<const float4*>(&HT[k * SR + r4]);
            ulonglong2 bq = *reinterpret_cast<const ulonglong2*>(&WB[k * W2S + tc16 * 4]);
            float b4 = WB[k * W2S + 64 + tc16];
            float a[4] = {av.x, av.y, av.z, av.w};
            #pragma unroll
            for (int j = 0; j < 4; j++) {
                u64 a2 = bcast2(a[j]);
                ffma2(acc2p[j][0], a2, bq.x);
                ffma2(acc2p[j][1], a2, bq.y);
                acc2s[j] = fmaf(a[j], b4, acc2s[j]);
            }
        }
        float* af2 = reinterpret_cast<float*>(acc2p);  // af2[j*4 + l]
        #pragma unroll
        for (int i = 0; i < 16; i++)
            af2[i] += __shfl_xor_sync(0xffffffffu, af2[i], 16);
        #pragma unroll
        for (int j = 0; j < 4; j++)
            acc2s[j] += __shfl_xor_sync(0xffffffffu, acc2s[j], 16);

        float4 b2v = __ldg(reinterpret_cast<const float4*>(&b2[tc16 * 4]));
        float  b2s = (tc16 < 12) ? __ldg(&b2[64 + tc16]) : 0.f;
        float bb2[5] = {b2v.x, b2v.y, b2v.z, b2v.w, b2s};
        if (p == 0) {
            #pragma unroll
            for (int j = 0; j < 4; j++) {
                #pragma unroll
                for (int l = 0; l < 4; l++)
                    zmu[j][l] = af2[j * 4 + l] + bb2[l];
                zmu[j][4] = acc2s[j] + bb2[4];
            }
        } else if (s == 0) {
            float z[4][5];
            #pragma unroll
            for (int j = 0; j < 4; j++) {
                float ee[5] = {ev[j].x, ev[j].y, ev[j].z, ev[j].w, e4[j]};
                #pragma unroll
                for (int l = 0; l < 4; l++)
                    z[j][l] = fmaf(ee[l], af2[j * 4 + l] + bb2[l], zmu[j][l]);
                z[j][4] = fmaf(ee[4], acc2s[j] + bb2[4], zmu[j][4]);
            }
            #pragma unroll
            for (int l = 0; l < 5; l++) {
                int c = (l < 4) ? tc16 * 4 + l : 64 + tc16;
                if (c < NF) {
                    float4 v = make_float4(z[0][l], z[1][l], z[2][l], z[3][l]);
                    *reinterpret_cast<float4*>(&ZS[c * SR + r4]) = v;
                }
            }
        }
    }

    // ===== Phase 3: W[64][384] = Z @ C2; out via i^q symmetry (split-k) =====
    const int cc0 = ch * 64 + tc16 * 4;
    for (int nc = 0; nc < KFOLD; nc += 128) {
        __syncthreads();
        for (int idx = tid; idx < NF * 32; idx += THREADS) {
            int k = idx >> 5, c4 = (idx & 31) * 4;
            *reinterpret_cast<float4*>(&CS[k * CSS + c4]) =
                *reinterpret_cast<const float4*>(&g_C2[k * KFOLD + nc + c4]);
        }
        __syncthreads();
        u64 acc3p[8][2];
        #pragma unroll
        for (int r = 0; r < 8; r++) { acc3p[r][0] = 0; acc3p[r][1] = 0; }
        const int kb3 = s * 38;
        #pragma unroll 2
        for (int kt = 0; kt < 38; kt++) {
            int k = kb3 + kt;
            float4 a0 = *reinterpret_cast<const float4*>(&ZS[k * SR + r8]);
            float4 a1 = *reinterpret_cast<const float4*>(&ZS[k * SR + r8 + 4]);
            ulonglong2 bq = *reinterpret_cast<const ulonglong2*>(&CS[k * CSS + cc0]);
            float a[8] = {a0.x, a0.y, a0.z, a0.w, a1.x, a1.y, a1.z, a1.w};
            #pragma unroll
            for (int r = 0; r < 8; r++) {
                u64 a2 = bcast2(a[r]);
                ffma2(acc3p[r][0], a2, bq.x);
                ffma2(acc3p[r][1], a2, bq.y);
            }
        }
        float* af3 = reinterpret_cast<float*>(acc3p);  // af3[r*4 + l]
        #pragma unroll
        for (int i = 0; i < 32; i++)
            af3[i] += __shfl_xor_sync(0xffffffffu, af3[i], 16);
        if (s == 0) {
            int c = nc + cc0;
            float sgn = (c < 192) ? 1.f : -1.f;
            #pragma unroll
            for (int r = 0; r < 8; r++) {
                size_t base = (size_t)(row0 + r8 + r) * IN_DIM;
                float4 v = make_float4(sgn * af3[r * 4 + 0], sgn * af3[r * 4 + 1],
                                       sgn * af3[r * 4 + 2], sgn * af3[r * 4 + 3]);
                *reinterpret_cast<float4*>(&out[base + c]) = v;
                *reinterpret_cast<float4*>(&out[base + c + 384]) =
                    make_float4(-v.x, -v.y, -v.z, -v.w);
            }
        }
    }
}

extern "C" void kernel_launch(void* const* d_in, const int* in_sizes, int n_in,
                              void* d_out, int out_size) {
    const float* x       = (const float*)d_in[0];
    const float* eps     = (const float*)d_in[1];
    const int*   indices = (const int*)  d_in[2];
    const float* mu_w1   = (const float*)d_in[3];
    const float* mu_b1   = (const float*)d_in[4];
    const float* mu_g    = (const float*)d_in[5];
    const float* mu_beta = (const float*)d_in[6];
    const float* mu_w2   = (const float*)d_in[7];
    const float* mu_b2   = (const float*)d_in[8];
    const float* sg_w1   = (const float*)d_in[9];
    const float* sg_b1   = (const float*)d_in[10];
    const float* sg_g    = (const float*)d_in[11];
    const float* sg_beta = (const float*)d_in[12];
    const float* sg_w2   = (const float*)d_in[13];
    const float* sg_b2   = (const float*)d_in[14];
    float* out = (float*)d_out;

    int n_rows = in_sizes[0] / IN_DIM;   // 32768

    cudaFuncSetAttribute(fused_kernel,
                         cudaFuncAttributeMaxDynamicSharedMemorySize, SMEM_BYTES);

    int pre_total = NC1 * KFOLD + 2 * HID * W1R + 2 * HID * NFP + NF * KFOLD;
    precompute_all<<<(pre_total + 255) / 256, 256>>>(indices, mu_w1, sg_w1, mu_w2, sg_w2);

    fused_kernel<<<n_rows / ROWS, THREADS, SMEM_BYTES>>>(
        x, eps,
        mu_b1, mu_g, mu_beta, mu_b2,
        sg_b1, sg_g, sg_beta, sg_b2,
        out);
}

// round 14
// speedup vs baseline: 1.0915x; 1.0915x over previous
#include <cuda_runtime.h>
#include <math.h>

#define IN_DIM 768
#define KSEL   38
#define NF     76
#define NFP    80
#define HID    256
#define ROWS   64
#define THREADS 512
#define KFOLD  384

// strides (floats)
#define SR   68       // col-major [.][row] buffers
#define W1S  260      // W1^T rows
#define W2S  84       // W2^T rows
#define CSS  132      // C tile rows
#define BSS  84       // B tile rows

// smem layout (float offsets)
#define OFF_XIN 0                       // [76][68]  = 5168 (col-major)
#define OFF_W   5168                    // aliased scratch (21504 floats)
#define OFF_XS  OFF_W                   //   [64][68] = 4352
#define OFF_BS  (OFF_W + 4352)          //   [64][84] = 5376
#define OFF_CS  OFF_W                   //   [76][132] = 10032
#define OFF_HT  (OFF_W + 21504)         // [256][68] = 17408 (col-major)
#define OFF_ZS  (OFF_HT + 17408)        // [76][68]  = 5168
#define OFF_LNS (OFF_ZS + 5168)         // [64][4]
#define SMEM_FLOATS (OFF_LNS + 256)
#define SMEM_BYTES  (SMEM_FLOATS * 4)   // 198016 B

typedef unsigned long long u64;

__device__ __forceinline__ void ffma2(u64& d, u64 a, u64 b) {
    asm("fma.rn.f32x2 %0, %1, %2, %0;" : "+l"(d) : "l"(a), "l"(b));
}
__device__ __forceinline__ u64 bcast2(float a) {
    u64 r;
    asm("mov.b64 %0, {%1, %1};" : "=l"(r) : "f"(a));
    return r;
}

// Precomputed tables
__device__ float g_B2[KFOLD * NFP];     // folded analysis [k][c]; pad cols 76..79 = 0
__device__ float g_C2[NF * KFOLD];      // folded synthesis [k][n]
__device__ float g_W1T[2][NF * HID];    // [p][i][j] = w1[j][i]
__device__ float g_W2T[2][HID * NFP];   // [p][k][c] = w2[c][k], pad 0

__global__ void precompute_all(const int* __restrict__ indices,
                               const float* __restrict__ mu_w1, const float* __restrict__ sg_w1,
                               const float* __restrict__ mu_w2, const float* __restrict__ sg_w2) {
    int t = blockIdx.x * blockDim.x + threadIdx.x;
    if (t < KFOLD * NFP) {
        int kk = t / NFP, k = t - kk * NFP;
        if (k >= NF) { g_B2[t] = 0.f; return; }
        int f = indices[(k < KSEL) ? k : (k - KSEL)];
        int m = (kk < 192) ? kk : kk - 192;
        int mm = (f * m) % IN_DIM;
        float s, c;
        sincospif((float)mm * (1.0f / 384.0f), &s, &c);
        float v;
        if (kk < 192) v = (k < KSEL) ? c : -s;    // d-row
        else          v = (k < KSEL) ? -s : -c;   // t-row
        g_B2[t] = v;
        return;
    }
    t -= KFOLD * NFP;
    if (t < NF * KFOLD) {
        int k = t / KFOLD, cc = t - k * KFOLD;
        int f = indices[(k < KSEL) ? k : (k - KSEL)];
        int m = (cc < 192) ? cc : cc - 192;
        int mm = (f * m) % IN_DIM;
        float s, c;
        sincospif((float)mm * (1.0f / 384.0f), &s, &c);
        float w = (f == 0 || 2 * f == IN_DIM) ? (1.0f / IN_DIM) : (2.0f / IN_DIM);
        float v;
        if (cc < 192) v = (k < KSEL) ? (w * c) : (-w * s);   // Wre
        else          v = (k < KSEL) ? (w * s) : (w * c);    // Wim
        g_C2[t] = v;
        return;
    }
    t -= NF * KFOLD;
    const int N1 = NF * HID;
    const int N2 = HID * NFP;
    if (t < 2 * N1) {
        int p = t / N1, r = t - p * N1;
        int i = r >> 8, j = r & 255;
        const float* w1 = p ? sg_w1 : mu_w1;
        g_W1T[p][r] = w1[j * NF + i];
        return;
    }
    t -= 2 * N1;
    if (t < 2 * N2) {
        int p = t / N2, r = t - p * N2;
        int k = r / NFP, c = r - k * NFP;
        const float* w2 = p ? sg_w2 : mu_w2;
        g_W2T[p][r] = (c < NF) ? w2[c * HID + k] : 0.f;
    }
}

__global__ __launch_bounds__(THREADS, 1)
void fused_kernel(const float* __restrict__ x,
                  const float* __restrict__ eps,
                  const float* __restrict__ mu_b1, const float* __restrict__ mu_g,
                  const float* __restrict__ mu_beta, const float* __restrict__ mu_b2,
                  const float* __restrict__ sg_b1, const float* __restrict__ sg_g,
                  const float* __restrict__ sg_beta, const float* __restrict__ sg_b2,
                  float* __restrict__ out)
{
    extern __shared__ float sm[];
    float* XIN = sm + OFF_XIN;
    float* WB  = sm + OFF_W;
    float* XS  = sm + OFF_XS;
    float* BS  = sm + OFF_BS;
    float* CS  = sm + OFF_CS;
    float* HT  = sm + OFF_HT;
    float* ZS  = sm + OFF_ZS;
    float* LNS = sm + OFF_LNS;

    const int tid  = threadIdx.x;
    const int w    = tid >> 5;
    const int lane = tid & 31;
    const int tc16 = lane & 15;
    const int s    = lane >> 4;
    const int r4   = w * 4;
    const int rg   = w & 7;
    const int ch   = w >> 3;
    const int r8   = rg * 8;
    const int row0 = blockIdx.x * ROWS;

    // ===== Phase 1: XIN[64][80] = fold(x)[64][384] @ B2 (split-k by s) =====
    u64 acc1p[4][2];
    float acc1s[4];
    #pragma unroll
    for (int j = 0; j < 4; j++) { acc1p[j][0] = 0; acc1p[j][1] = 0; acc1s[j] = 0.f; }

    for (int kb = 0; kb < KFOLD; kb += 64) {
        __syncthreads();
        {   // stage folded differences transposed: XS[k][row]
            int r = tid & 63, cc = (tid >> 6) * 8;
            const float* xp = &x[(size_t)(row0 + r) * IN_DIM + kb + cc];
            float4 v0 = *reinterpret_cast<const float4*>(xp);
            float4 v1 = *reinterpret_cast<const float4*>(xp + 4);
            float4 w0 = *reinterpret_cast<const float4*>(xp + 384);
            float4 w1 = *reinterpret_cast<const float4*>(xp + 388);
            XS[(cc + 0) * SR + r] = v0.x - w0.x;
            XS[(cc + 1) * SR + r] = v0.y - w0.y;
            XS[(cc + 2) * SR + r] = v0.z - w0.z;
            XS[(cc + 3) * SR + r] = v0.w - w0.w;
            XS[(cc + 4) * SR + r] = v1.x - w1.x;
            XS[(cc + 5) * SR + r] = v1.y - w1.y;
            XS[(cc + 6) * SR + r] = v1.z - w1.z;
            XS[(cc + 7) * SR + r] = v1.w - w1.w;
        }
        for (int idx = tid; idx < 64 * 20; idx += THREADS) {
            int k = idx / 20, c4 = (idx - k * 20) * 4;
            *reinterpret_cast<float4*>(&BS[k * BSS + c4]) =
                *reinterpret_cast<const float4*>(&g_B2[(kb + k) * NFP + c4]);
        }
        __syncthreads();
        const int k0 = s * 32;
        #pragma unroll 4
        for (int kt = 0; kt < 32; kt++) {
            int kk = k0 + kt;
            float4 av = *reinterpret_cast<const float4*>(&XS[kk * SR + r4]);
            ulonglong2 bq = *reinterpret_cast<const ulonglong2*>(&BS[kk * BSS + tc16 * 4]);
            float b4 = BS[kk * BSS + 64 + tc16];
            float a[4] = {av.x, av.y, av.z, av.w};
            #pragma unroll
            for (int j = 0; j < 4; j++) {
                u64 a2 = bcast2(a[j]);
                ffma2(acc1p[j][0], a2, bq.x);
                ffma2(acc1p[j][1], a2, bq.y);
                acc1s[j] = fmaf(a[j], b4, acc1s[j]);
            }
        }
    }
    {
        float* af = reinterpret_cast<float*>(acc1p);   // af[j*4 + l]
        #pragma unroll
        for (int i = 0; i < 16; i++)
            af[i] += __shfl_xor_sync(0xffffffffu, af[i], 16);
        #pragma unroll
        for (int j = 0; j < 4; j++)
            acc1s[j] += __shfl_xor_sync(0xffffffffu, acc1s[j], 16);
        if (s == 0) {
            #pragma unroll
            for (int l = 0; l < 4; l++) {
                int c = tc16 * 4 + l;
                *reinterpret_cast<float4*>(&XIN[c * SR + r4]) =
                    make_float4(af[l], af[4 + l], af[8 + l], af[12 + l]);
            }
            int c = 64 + tc16;
            if (c < NF)
                *reinterpret_cast<float4*>(&XIN[c * SR + r4]) =
                    make_float4(acc1s[0], acc1s[1], acc1s[2], acc1s[3]);
        }
    }

    // ===== Phase 2: two MLPs =====
    float zmu[4][5];
    #pragma unroll 1
    for (int p = 0; p < 2; p++) {
        const float* b1 = p ? sg_b1 : mu_b1;
        const float* gp = p ? sg_g : mu_g;
        const float* bp = p ? sg_beta : mu_beta;
        const float* b2 = p ? sg_b2 : mu_b2;
        const float* w1t = g_W1T[p];
        const float* w2t = g_W2T[p];

        __syncthreads();   // XIN ready (p=0) / WB free
        for (int idx = tid; idx < NF * 64; idx += THREADS) {
            int i = idx >> 6, j4 = (idx & 63) * 4;
            *reinterpret_cast<float4*>(&WB[i * W1S + j4]) =
                *reinterpret_cast<const float4*>(&w1t[i * HID + j4]);
        }
        __syncthreads();

        // GEMM1: H[64][256] = XIN @ W1^T — 8-row warp tiles, split-k
        const int c0 = ch * 128 + tc16 * 8;
        u64 accp[8][4];
        #pragma unroll
        for (int r = 0; r < 8; r++)
            #pragma unroll
            for (int q = 0; q < 4; q++) accp[r][q] = 0;
        const int i0 = s * 38;
        #pragma unroll 2
        for (int it = 0; it < 38; it++) {
            int i = i0 + it;
            float4 a0 = *reinterpret_cast<const float4*>(&XIN[i * SR + r8]);
            float4 a1 = *reinterpret_cast<const float4*>(&XIN[i * SR + r8 + 4]);
            const float* wrow = &WB[i * W1S + c0];
            ulonglong2 bq0 = *reinterpret_cast<const ulonglong2*>(wrow);
            ulonglong2 bq1 = *reinterpret_cast<const ulonglong2*>(wrow + 4);
            float a[8] = {a0.x, a0.y, a0.z, a0.w, a1.x, a1.y, a1.z, a1.w};
            #pragma unroll
            for (int r = 0; r < 8; r++) {
                u64 a2 = bcast2(a[r]);
                ffma2(accp[r][0], a2, bq0.x);
                ffma2(accp[r][1], a2, bq0.y);
                ffma2(accp[r][2], a2, bq1.x);
                ffma2(accp[r][3], a2, bq1.y);
            }
        }
        float* af = reinterpret_cast<float*>(accp);    // af[r*8 + c]
        #pragma unroll
        for (int i = 0; i < 64; i++)
            af[i] += __shfl_xor_sync(0xffffffffu, af[i], 16);

        // bias + per-warp partial LN stats
        {
            float4 q0 = __ldg(reinterpret_cast<const float4*>(&b1[c0]));
            float4 q1 = __ldg(reinterpret_cast<const float4*>(&b1[c0 + 4]));
            float bb[8] = {q0.x, q0.y, q0.z, q0.w, q1.x, q1.y, q1.z, q1.w};
            float sv[8], sq[8];
            #pragma unroll
            for (int r = 0; r < 8; r++) {
                sv[r] = 0.f; sq[r] = 0.f;
                #pragma unroll
                for (int c = 0; c < 8; c++) {
                    float v = af[r * 8 + c] + bb[c];
                    af[r * 8 + c] = v;
                    sv[r] += v;
                    sq[r] = fmaf(v, v, sq[r]);
                }
            }
            #pragma unroll
            for (int o = 1; o <= 8; o <<= 1) {
                #pragma unroll
                for (int r = 0; r < 8; r++) {
                    sv[r] += __shfl_xor_sync(0xffffffffu, sv[r], o);
                    sq[r] += __shfl_xor_sync(0xffffffffu, sq[r], o);
                }
            }
            if (lane == 0) {
                #pragma unroll
                for (int r = 0; r < 8; r++)
                    *reinterpret_cast<float2*>(&LNS[(r8 + r) * 4 + ch * 2]) =
                        make_float2(sv[r], sq[r]);
            }
        }
        __syncthreads();   // LNS ready; GEMM1 WB reads complete

        // stage W2 now — overlaps the LDGs with the LN/GELU math below
        for (int idx = tid; idx < HID * 20; idx += THREADS) {
            int k = idx / 20, c4 = (idx - k * 20) * 4;
            *reinterpret_cast<float4*>(&WB[k * W2S + c4]) =
                *reinterpret_cast<const float4*>(&w2t[k * NFP + c4]);
        }
        {
            float4 g0 = __ldg(reinterpret_cast<const float4*>(&gp[c0]));
            float4 g1 = __ldg(reinterpret_cast<const float4*>(&gp[c0 + 4]));
            float4 e0 = __ldg(reinterpret_cast<const float4*>(&bp[c0]));
            float4 e1 = __ldg(reinterpret_cast<const float4*>(&bp[c0 + 4]));
            float gg[8] = {g0.x, g0.y, g0.z, g0.w, g1.x, g1.y, g1.z, g1.w};
            float bt[8] = {e0.x, e0.y, e0.z, e0.w, e1.x, e1.y, e1.z, e1.w};
            #pragma unroll
            for (int r = 0; r < 8; r++) {
                float4 st = *reinterpret_cast<const float4*>(&LNS[(r8 + r) * 4]);
                float mean = (st.x + st.z) * (1.f / HID);
                float inv  = rsqrtf((st.y + st.w) * (1.f / HID) - mean * mean + 1e-5f);
                #pragma unroll
                for (int c = 0; c < 8; c++) {
                    float hn = (af[r * 8 + c] - mean) * inv * gg[c] + bt[c];
                    af[r * 8 + c] = 0.5f * hn * (1.f + erff(hn * 0.70710678118654752f));
                }
            }
        }
        if (s == 0) {
            #pragma unroll
            for (int c = 0; c < 8; c++) {
                *reinterpret_cast<float4*>(&HT[(c0 + c) * SR + r8]) =
                    make_float4(af[c], af[8 + c], af[16 + c], af[24 + c]);
                *reinterpret_cast<float4*>(&HT[(c0 + c) * SR + r8 + 4]) =
                    make_float4(af[32 + c], af[40 + c], af[48 + c], af[56 + c]);
            }
        }
        __syncthreads();   // HT + W2 ready

        // eps prefetch (consumed in p==1 epilogue) — hides LDG behind GEMM2
        float4 ev[4]; float e4[4];
        if (p == 1) {
            #pragma unroll
            for (int j = 0; j < 4; j++) {
                int row = row0 + r4 + j;
                ev[j] = __ldg(reinterpret_cast<const float4*>(&eps[(size_t)row * NF + tc16 * 4]));
                e4[j] = (tc16 < 12) ? __ldg(&eps[(size_t)row * NF + 64 + tc16]) : 0.f;
            }
        }

        // GEMM2: Z[64][80] = gelu(H) @ W2^T (split-k by s)
        u64 acc2p[4][2];
        float acc2s[4];
        #pragma unroll
        for (int j = 0; j < 4; j++) { acc2p[j][0] = 0; acc2p[j][1] = 0; acc2s[j] = 0.f; }
        const int kbase = s * 128;
        #pragma unroll 4
        for (int kt = 0; kt < 128; kt++) {
            int k = kbase + kt;
            float4 av = *reinterpret_cast<const float4*>(&HT[k * SR + r4]);
            ulonglong2 bq = *reinterpret_cast<const ulonglong2*>(&WB[k * W2S + tc16 * 4]);
            float b4 = WB[k * W2S + 64 + tc16];
            float a[4] = {av.x, av.y, av.z, av.w};
            #pragma unroll
            for (int j = 0; j < 4; j++) {
                u64 a2 = bcast2(a[j]);
                ffma2(acc2p[j][0], a2, bq.x);
                ffma2(acc2p[j][1], a2, bq.y);
                acc2s[j] = fmaf(a[j], b4, acc2s[j]);
            }
        }
        float* af2 = reinterpret_cast<float*>(acc2p);  // af2[j*4 + l]
        #pragma unroll
        for (int i = 0; i < 16; i++)
            af2[i] += __shfl_xor_sync(0xffffffffu, af2[i], 16);
        #pragma unroll
        for (int j = 0; j < 4; j++)
            acc2s[j] += __shfl_xor_sync(0xffffffffu, acc2s[j], 16);

        float4 b2v = __ldg(reinterpret_cast<const float4*>(&b2[tc16 * 4]));
        float  b2s = (tc16 < 12) ? __ldg(&b2[64 + tc16]) : 0.f;
        float bb2[5] = {b2v.x, b2v.y, b2v.z, b2v.w, b2s};
        if (p == 0) {
            #pragma unroll
            for (int j = 0; j < 4; j++) {
                #pragma unroll
                for (int l = 0; l < 4; l++)
                    zmu[j][l] = af2[j * 4 + l] + bb2[l];
                zmu[j][4] = acc2s[j] + bb2[4];
            }
        } else if (s == 0) {
            float z[4][5];
            #pragma unroll
            for (int j = 0; j < 4; j++) {
                float ee[5] = {ev[j].x, ev[j].y, ev[j].z, ev[j].w, e4[j]};
                #pragma unroll
                for (int l = 0; l < 4; l++)
                    z[j][l] = fmaf(ee[l], af2[j * 4 + l] + bb2[l], zmu[j][l]);
                z[j][4] = fmaf(ee[4], acc2s[j] + bb2[4], zmu[j][4]);
            }
            #pragma unroll
            for (int l = 0; l < 5; l++) {
                int c = (l < 4) ? tc16 * 4 + l : 64 + tc16;
                if (c < NF) {
                    float4 v = make_float4(z[0][l], z[1][l], z[2][l], z[3][l]);
                    *reinterpret_cast<float4*>(&ZS[c * SR + r4]) = v;
                }
            }
        }
    }

    // ===== Phase 3: W[64][384] = Z @ C2; out via i^q symmetry (split-k) =====
    const int cc0 = ch * 64 + tc16 * 4;
    for (int nc = 0; nc < KFOLD; nc += 128) {
        __syncthreads();   // ZS visible / WB free
        for (int idx = tid; idx < NF * 32; idx += THREADS) {
            int k = idx >> 5, c4 = (idx & 31) * 4;
            *reinterpret_cast<float4*>(&CS[k * CSS + c4]) =
                *reinterpret_cast<const float4*>(&g_C2[k * KFOLD + nc + c4]);
        }
        __syncthreads();
        u64 acc3p[8][2];
        #pragma unroll
        for (int r = 0; r < 8; r++) { acc3p[r][0] = 0; acc3p[r][1] = 0; }
        const int kb3 = s * 38;
        #pragma unroll 2
        for (int kt = 0; kt < 38; kt++) {
            int k = kb3 + kt;
            float4 a0 = *reinterpret_cast<const float4*>(&ZS[k * SR + r8]);
            float4 a1 = *reinterpret_cast<const float4*>(&ZS[k * SR + r8 + 4]);
            ulonglong2 bq = *reinterpret_cast<const ulonglong2*>(&CS[k * CSS + cc0]);
            float a[8] = {a0.x, a0.y, a0.z, a0.w, a1.x, a1.y, a1.z, a1.w};
            #pragma unroll
            for (int r = 0; r < 8; r++) {
                u64 a2 = bcast2(a[r]);
                ffma2(acc3p[r][0], a2, bq.x);
                ffma2(acc3p[r][1], a2, bq.y);
            }
        }
        float* af3 = reinterpret_cast<float*>(acc3p);  // af3[r*4 + l]
        #pragma unroll
        for (int i = 0; i < 32; i++)
            af3[i] += __shfl_xor_sync(0xffffffffu, af3[i], 16);
        if (s == 0) {
            int c = nc + cc0;
            float sgn = (c < 192) ? 1.f : -1.f;
            #pragma unroll
            for (int r = 0; r < 8; r++) {
                size_t base = (size_t)(row0 + r8 + r) * IN_DIM;
                float4 v = make_float4(sgn * af3[r * 4 + 0], sgn * af3[r * 4 + 1],
                                       sgn * af3[r * 4 + 2], sgn * af3[r * 4 + 3]);
                *reinterpret_cast<float4*>(&out[base + c]) = v;
                *reinterpret_cast<float4*>(&out[base + c + 384]) =
                    make_float4(-v.x, -v.y, -v.z, -v.w);
            }
        }
    }
}

extern "C" void kernel_launch(void* const* d_in, const int* in_sizes, int n_in,
                              void* d_out, int out_size) {
    const float* x       = (const float*)d_in[0];
    const float* eps     = (const float*)d_in[1];
    const int*   indices = (const int*)  d_in[2];
    const float* mu_w1   = (const float*)d_in[3];
    const float* mu_b1   = (const float*)d_in[4];
    const float* mu_g    = (const float*)d_in[5];
    const float* mu_beta = (const float*)d_in[6];
    const float* mu_w2   = (const float*)d_in[7];
    const float* mu_b2   = (const float*)d_in[8];
    const float* sg_w1   = (const float*)d_in[9];
    const float* sg_b1   = (const float*)d_in[10];
    const float* sg_g    = (const float*)d_in[11];
    const float* sg_beta = (const float*)d_in[12];
    const float* sg_w2   = (const float*)d_in[13];
    const float* sg_b2   = (const float*)d_in[14];
    float* out = (float*)d_out;

    int n_rows = in_sizes[0] / IN_DIM;   // 32768

    cudaFuncSetAttribute(fused_kernel,
                         cudaFuncAttributeMaxDynamicSharedMemorySize, SMEM_BYTES);

    int pre_total = KFOLD * NFP + NF * KFOLD + 2 * NF * HID + 2 * HID * NFP;
    precompute_all<<<(pre_total + 255) / 256, 256>>>(indices, mu_w1, sg_w1, mu_w2, sg_w2);

    fused_kernel<<<n_rows / ROWS, THREADS, SMEM_BYTES>>>(
        x, eps,
        mu_b1, mu_g, mu_beta, mu_b2,
        sg_b1, sg_g, sg_beta, sg_b2,
        out);
}

// round 16
// speedup vs baseline: 1.1606x; 1.0633x over previous
#include <cuda_runtime.h>
#include <math.h>

#define IN_DIM 768
#define KSEL   38
#define NF     76
#define NFP    80
#define HID    256
#define ROWS   64
#define KFOLD  384
#define NTILES 512            // 32768 / 64

// ---- K2 smem (floats) ----
#define SR   68
#define W1S  260
#define W2S  84
#define OFF_XIN 0                       // [76][68]  = 5168
#define OFF_W   5168                    // 21504 (W1 then W2 staged)
#define OFF_HT  26672                   // [256][68] = 17408
#define OFF_LNS 44080                   // [64][4]   = 256
#define K2_SMEM_FLOATS 44336
#define K2_SMEM_BYTES  (K2_SMEM_FLOATS * 4)   // 177344 B

typedef unsigned long long u64;

__device__ __forceinline__ void ffma2(u64& d, u64 a, u64 b) {
    asm("fma.rn.f32x2 %0, %1, %2, %0;" : "+l"(d) : "l"(a), "l"(b));
}
__device__ __forceinline__ u64 bcast2(float a) {
    u64 r;
    asm("mov.b64 %0, {%1, %1};" : "=l"(r) : "f"(a));
    return r;
}

// Precomputed tables + inter-kernel scratch (device globals: no allocation)
__device__ float g_B2[KFOLD * NFP];     // folded analysis [k][c]; pad cols 76..79 = 0
__device__ float g_C2[NF * KFOLD];      // folded synthesis [k][n]
__device__ float g_W1T[2][NF * HID];    // [p][i][j] = w1[j][i]
__device__ float g_W2T[2][HID * NFP];   // [p][k][c] = w2[c][k], pad 0
__device__ float g_XIN[NTILES * NFP * ROWS];  // [tile][c][row]
__device__ float g_Z[NTILES * NFP * ROWS];    // [tile][c][row]

__global__ void precompute_all(const int* __restrict__ indices,
                               const float* __restrict__ mu_w1, const float* __restrict__ sg_w1,
                               const float* __restrict__ mu_w2, const float* __restrict__ sg_w2) {
    int t = blockIdx.x * blockDim.x + threadIdx.x;
    if (t < KFOLD * NFP) {
        int kk = t / NFP, k = t - kk * NFP;
        if (k >= NF) { g_B2[t] = 0.f; return; }
        int f = indices[(k < KSEL) ? k : (k - KSEL)];
        int m = (kk < 192) ? kk : kk - 192;
        int mm = (f * m) % IN_DIM;
        float s, c;
        sincospif((float)mm * (1.0f / 384.0f), &s, &c);
        float v;
        if (kk < 192) v = (k < KSEL) ? c : -s;
        else          v = (k < KSEL) ? -s : -c;
        g_B2[t] = v;
        return;
    }
    t -= KFOLD * NFP;
    if (t < NF * KFOLD) {
        int k = t / KFOLD, cc = t - k * KFOLD;
        int f = indices[(k < KSEL) ? k : (k - KSEL)];
        int m = (cc < 192) ? cc : cc - 192;
        int mm = (f * m) % IN_DIM;
        float s, c;
        sincospif((float)mm * (1.0f / 384.0f), &s, &c);
        float w = (f == 0 || 2 * f == IN_DIM) ? (1.0f / IN_DIM) : (2.0f / IN_DIM);
        float v;
        if (cc < 192) v = (k < KSEL) ? (w * c) : (-w * s);
        else          v = (k < KSEL) ? (w * s) : (w * c);
        g_C2[t] = v;
        return;
    }
    t -= NF * KFOLD;
    const int N1 = NF * HID;
    const int N2 = HID * NFP;
    if (t < 2 * N1) {
        int p = t / N1, r = t - p * N1;
        int i = r >> 8, j = r & 255;
        const float* w1 = p ? sg_w1 : mu_w1;
        g_W1T[p][r] = w1[j * NF + i];
        return;
    }
    t -= 2 * N1;
    if (t < 2 * N2) {
        int p = t / N2, r = t - p * N2;
        int k = r / NFP, c = r - k * NFP;
        const float* w2 = p ? sg_w2 : mu_w2;
        g_W2T[p][r] = (c < NF) ? w2[c * HID + k] : 0.f;
    }
}

// =============== K1: XIN = fold(x) @ B2  (high-occupancy DFT) ===============
__global__ __launch_bounds__(256, 4)
void k1_dft(const float* __restrict__ x) {
    __shared__ float XS[64 * SR];       // [k][row]
    __shared__ float BS[64 * 84];       // [k][c]

    const int tid = threadIdx.x;
    const int tr = tid >> 4;            // 0..15
    const int tc = tid & 15;
    const int r4 = tr * 4;
    const int row0 = blockIdx.x * ROWS;

    u64 accp[4][2];
    float accs[4];
    #pragma unroll
    for (int j = 0; j < 4; j++) { accp[j][0] = 0; accp[j][1] = 0; accs[j] = 0.f; }

    for (int kb = 0; kb < KFOLD; kb += 64) {
        __syncthreads();
        {   // stage folded x transposed: XS[k][row]; each thread 16 k for one row
            int r = tid & 63, cc = (tid >> 6) * 16;
            const float* xp = &x[(size_t)(row0 + r) * IN_DIM + kb + cc];
            #pragma unroll
            for (int h = 0; h < 4; h++) {
                float4 v = *reinterpret_cast<const float4*>(xp + h * 4);
                float4 q = *reinterpret_cast<const float4*>(xp + h * 4 + 384);
                XS[(cc + h * 4 + 0) * SR + r] = v.x - q.x;
                XS[(cc + h * 4 + 1) * SR + r] = v.y - q.y;
                XS[(cc + h * 4 + 2) * SR + r] = v.z - q.z;
                XS[(cc + h * 4 + 3) * SR + r] = v.w - q.w;
            }
        }
        for (int idx = tid; idx < 64 * 20; idx += 256) {
            int k = idx / 20, c4 = (idx - k * 20) * 4;
            *reinterpret_cast<float4*>(&BS[k * 84 + c4]) =
                *reinterpret_cast<const float4*>(&g_B2[(kb + k) * NFP + c4]);
        }
        __syncthreads();
        #pragma unroll 4
        for (int kk = 0; kk < 64; kk++) {
            float4 av = *reinterpret_cast<const float4*>(&XS[kk * SR + r4]);
            ulonglong2 bq = *reinterpret_cast<const ulonglong2*>(&BS[kk * 84 + tc * 4]);
            float b4 = BS[kk * 84 + 64 + tc];
            float a[4] = {av.x, av.y, av.z, av.w};
            #pragma unroll
            for (int j = 0; j < 4; j++) {
                u64 a2 = bcast2(a[j]);
                ffma2(accp[j][0], a2, bq.x);
                ffma2(accp[j][1], a2, bq.y);
                accs[j] = fmaf(a[j], b4, accs[j]);
            }
        }
    }
    {
        float* af = reinterpret_cast<float*>(accp);   // af[j*4 + l]
        float* xg = &g_XIN[(size_t)blockIdx.x * (NFP * ROWS)];
        #pragma unroll
        for (int l = 0; l < 4; l++) {
            int c = tc * 4 + l;
            *reinterpret_cast<float4*>(&xg[c * 64 + r4]) =
                make_float4(af[l], af[4 + l], af[8 + l], af[12 + l]);
        }
        *reinterpret_cast<float4*>(&xg[(64 + tc) * 64 + r4]) =
            make_float4(accs[0], accs[1], accs[2], accs[3]);
    }
}

// =============== K2: two MLPs (XIN -> Z) ===============
__global__ __launch_bounds__(512, 1)
void k2_mlp(const float* __restrict__ eps,
            const float* __restrict__ mu_b1, const float* __restrict__ mu_g,
            const float* __restrict__ mu_beta, const float* __restrict__ mu_b2,
            const float* __restrict__ sg_b1, const float* __restrict__ sg_g,
            const float* __restrict__ sg_beta, const float* __restrict__ sg_b2)
{
    extern __shared__ float sm[];
    float* XIN = sm + OFF_XIN;
    float* WB  = sm + OFF_W;
    float* HT  = sm + OFF_HT;
    float* LNS = sm + OFF_LNS;

    const int tid  = threadIdx.x;
    const int w    = tid >> 5;
    const int lane = tid & 31;
    const int tc16 = lane & 15;
    const int s    = lane >> 4;
    const int r4   = w * 4;
    const int rg   = w & 7;
    const int ch   = w >> 3;
    const int r8   = rg * 8;
    const int row0 = blockIdx.x * ROWS;
    const float* xg = &g_XIN[(size_t)blockIdx.x * (NFP * ROWS)];

    // stage XIN col-major (coalesced float4)
    for (int idx = tid; idx < NF * 16; idx += 512) {
        int c = idx >> 4, rr = (idx & 15) * 4;
        *reinterpret_cast<float4*>(&XIN[c * SR + rr]) =
            *reinterpret_cast<const float4*>(&xg[c * 64 + rr]);
    }

    float zmu[4][5];
    #pragma unroll 1
    for (int p = 0; p < 2; p++) {
        const float* b1 = p ? sg_b1 : mu_b1;
        const float* gp = p ? sg_g : mu_g;
        const float* bp = p ? sg_beta : mu_beta;
        const float* b2 = p ? sg_b2 : mu_b2;
        const float* w1t = g_W1T[p];
        const float* w2t = g_W2T[p];

        __syncthreads();   // XIN ready (p=0) / WB free
        for (int idx = tid; idx < NF * 64; idx += 512) {
            int i = idx >> 6, j4 = (idx & 63) * 4;
            *reinterpret_cast<float4*>(&WB[i * W1S + j4]) =
                *reinterpret_cast<const float4*>(&w1t[i * HID + j4]);
        }
        __syncthreads();

        // GEMM1: H[64][256] = XIN @ W1^T — 8-row warp tiles, split-k
        const int c0 = ch * 128 + tc16 * 8;
        u64 accp[8][4];
        #pragma unroll
        for (int r = 0; r < 8; r++)
            #pragma unroll
            for (int q = 0; q < 4; q++) accp[r][q] = 0;
        const int i0 = s * 38;
        #pragma unroll 2
        for (int it = 0; it < 38; it++) {
            int i = i0 + it;
            float4 a0 = *reinterpret_cast<const float4*>(&XIN[i * SR + r8]);
            float4 a1 = *reinterpret_cast<const float4*>(&XIN[i * SR + r8 + 4]);
            const float* wrow = &WB[i * W1S + c0];
            ulonglong2 bq0 = *reinterpret_cast<const ulonglong2*>(wrow);
            ulonglong2 bq1 = *reinterpret_cast<const ulonglong2*>(wrow + 4);
            float a[8] = {a0.x, a0.y, a0.z, a0.w, a1.x, a1.y, a1.z, a1.w};
            #pragma unroll
            for (int r = 0; r < 8; r++) {
                u64 a2 = bcast2(a[r]);
                ffma2(accp[r][0], a2, bq0.x);
                ffma2(accp[r][1], a2, bq0.y);
                ffma2(accp[r][2], a2, bq1.x);
                ffma2(accp[r][3], a2, bq1.y);
            }
        }
        float* af = reinterpret_cast<float*>(accp);    // af[r*8 + c]
        #pragma unroll
        for (int i = 0; i < 64; i++)
            af[i] += __shfl_xor_sync(0xffffffffu, af[i], 16);

        // bias + per-warp partial LN stats
        {
            float4 q0 = __ldg(reinterpret_cast<const float4*>(&b1[c0]));
            float4 q1 = __ldg(reinterpret_cast<const float4*>(&b1[c0 + 4]));
            float bb[8] = {q0.x, q0.y, q0.z, q0.w, q1.x, q1.y, q1.z, q1.w};
            float sv[8], sq[8];
            #pragma unroll
            for (int r = 0; r < 8; r++) {
                sv[r] = 0.f; sq[r] = 0.f;
                #pragma unroll
                for (int c = 0; c < 8; c++) {
                    float v = af[r * 8 + c] + bb[c];
                    af[r * 8 + c] = v;
                    sv[r] += v;
                    sq[r] = fmaf(v, v, sq[r]);
                }
            }
            #pragma unroll
            for (int o = 1; o <= 8; o <<= 1) {
                #pragma unroll
                for (int r = 0; r < 8; r++) {
                    sv[r] += __shfl_xor_sync(0xffffffffu, sv[r], o);
                    sq[r] += __shfl_xor_sync(0xffffffffu, sq[r], o);
                }
            }
            if (lane == 0) {
                #pragma unroll
                for (int r = 0; r < 8; r++)
                    *reinterpret_cast<float2*>(&LNS[(r8 + r) * 4 + ch * 2]) =
                        make_float2(sv[r], sq[r]);
            }
        }
        __syncthreads();   // LNS ready; GEMM1 WB reads complete

        // stage W2 (overlaps LN/GELU math)
        for (int idx = tid; idx < HID * 20; idx += 512) {
            int k = idx / 20, c4 = (idx - k * 20) * 4;
            *reinterpret_cast<float4*>(&WB[k * W2S + c4]) =
                *reinterpret_cast<const float4*>(&w2t[k * NFP + c4]);
        }
        {
            float4 g0 = __ldg(reinterpret_cast<const float4*>(&gp[c0]));
            float4 g1 = __ldg(reinterpret_cast<const float4*>(&gp[c0 + 4]));
            float4 e0 = __ldg(reinterpret_cast<const float4*>(&bp[c0]));
            float4 e1 = __ldg(reinterpret_cast<const float4*>(&bp[c0 + 4]));
            float gg[8] = {g0.x, g0.y, g0.z, g0.w, g1.x, g1.y, g1.z, g1.w};
            float bt[8] = {e0.x, e0.y, e0.z, e0.w, e1.x, e1.y, e1.z, e1.w};
            #pragma unroll
            for (int r = 0; r < 8; r++) {
                float4 st = *reinterpret_cast<const float4*>(&LNS[(r8 + r) * 4]);
                float mean = (st.x + st.z) * (1.f / HID);
                float inv  = rsqrtf((st.y + st.w) * (1.f / HID) - mean * mean + 1e-5f);
                #pragma unroll
                for (int c = 0; c < 8; c++) {
                    float hn = (af[r * 8 + c] - mean) * inv * gg[c] + bt[c];
                    af[r * 8 + c] = 0.5f * hn * (1.f + erff(hn * 0.70710678118654752f));
                }
            }
        }
        if (s == 0) {
            #pragma unroll
            for (int c = 0; c < 8; c++) {
                *reinterpret_cast<float4*>(&HT[(c0 + c) * SR + r8]) =
                    make_float4(af[c], af[8 + c], af[16 + c], af[24 + c]);
                *reinterpret_cast<float4*>(&HT[(c0 + c) * SR + r8 + 4]) =
                    make_float4(af[32 + c], af[40 + c], af[48 + c], af[56 + c]);
            }
        }
        __syncthreads();   // HT + W2 ready

        float4 ev[4]; float e4[4];
        if (p == 1) {
            #pragma unroll
            for (int j = 0; j < 4; j++) {
                int row = row0 + r4 + j;
                ev[j] = __ldg(reinterpret_cast<const float4*>(&eps[(size_t)row * NF + tc16 * 4]));
                e4[j] = (tc16 < 12) ? __ldg(&eps[(size_t)row * NF + 64 + tc16]) : 0.f;
            }
        }

        // GEMM2: Z[64][80] = gelu(H) @ W2^T (split-k by s)
        u64 acc2p[4][2];
        float acc2s[4];
        #pragma unroll
        for (int j = 0; j < 4; j++) { acc2p[j][0] = 0; acc2p[j][1] = 0; acc2s[j] = 0.f; }
        const int kbase = s * 128;
        #pragma unroll 4
        for (int kt = 0; kt < 128; kt++) {
            int k = kbase + kt;
            float4 av = *reinterpret_cast<const float4*>(&HT[k * SR + r4]);
            ulonglong2 bq = *reinterpret_cast<const ulonglong2*>(&WB[k * W2S + tc16 * 4]);
            float b4 = WB[k * W2S + 64 + tc16];
            float a[4] = {av.x, av.y, av.z, av.w};
            #pragma unroll
            for (int j = 0; j < 4; j++) {
                u64 a2 = bcast2(a[j]);
                ffma2(acc2p[j][0], a2, bq.x);
                ffma2(acc2p[j][1], a2, bq.y);
                acc2s[j] = fmaf(a[j], b4, acc2s[j]);
            }
        }
        float* af2 = reinterpret_cast<float*>(acc2p);  // af2[j*4 + l]
        #pragma unroll
        for (int i = 0; i < 16; i++)
            af2[i] += __shfl_xor_sync(0xffffffffu, af2[i], 16);
        #pragma unroll
        for (int j = 0; j < 4; j++)
            acc2s[j] += __shfl_xor_sync(0xffffffffu, acc2s[j], 16);

        float4 b2v = __ldg(reinterpret_cast<const float4*>(&b2[tc16 * 4]));
        float  b2s = (tc16 < 12) ? __ldg(&b2[64 + tc16]) : 0.f;
        float bb2[5] = {b2v.x, b2v.y, b2v.z, b2v.w, b2s};
        if (p == 0) {
            #pragma unroll
            for (int j = 0; j < 4; j++) {
                #pragma unroll
                for (int l = 0; l < 4; l++)
                    zmu[j][l] = af2[j * 4 + l] + bb2[l];
                zmu[j][4] = acc2s[j] + bb2[4];
            }
        } else if (s == 0) {
            float z[4][5];
            #pragma unroll
            for (int j = 0; j < 4; j++) {
                float ee[5] = {ev[j].x, ev[j].y, ev[j].z, ev[j].w, e4[j]};
                #pragma unroll
                for (int l = 0; l < 4; l++)
                    z[j][l] = fmaf(ee[l], af2[j * 4 + l] + bb2[l], zmu[j][l]);
                z[j][4] = fmaf(ee[4], acc2s[j] + bb2[4], zmu[j][4]);
            }
            float* zg = &g_Z[(size_t)blockIdx.x * (NFP * ROWS)];
            #pragma unroll
            for (int l = 0; l < 5; l++) {
                int c = (l < 4) ? tc16 * 4 + l : 64 + tc16;
                if (c < NF)
                    *reinterpret_cast<float4*>(&zg[c * 64 + r4]) =
                        make_float4(z[0][l], z[1][l], z[2][l], z[3][l]);
            }
        }
    }
}

// =============== K3: out = Z @ C2 with i^q symmetry (high-occupancy) ===============
__global__ __launch_bounds__(256, 4)
void k3_synth(float* __restrict__ out) {
    __shared__ float ZS[NF * SR];       // [k][row]
    __shared__ float CS[NF * SR];       // [k][c-chunk]

    const int tid = threadIdx.x;
    const int tr = tid >> 4;
    const int tc = tid & 15;
    const int r4 = tr * 4;
    const int row0 = blockIdx.x * ROWS;
    const float* zg = &g_Z[(size_t)blockIdx.x * (NFP * ROWS)];

    // stage Z tile (coalesced float4)
    for (int idx = tid; idx < NF * 16; idx += 256) {
        int c = idx >> 4, rr = (idx & 15) * 4;
        *reinterpret_cast<float4*>(&ZS[c * SR + rr]) =
            *reinterpret_cast<const float4*>(&zg[c * 64 + rr]);
    }

    for (int nc = 0; nc < KFOLD; nc += 64) {
        __syncthreads();   // ZS ready (first) / prev CS reads done
        for (int idx = tid; idx < NF * 16; idx += 256) {
            int k = idx >> 4, c4 = (idx & 15) * 4;
            *reinterpret_cast<float4*>(&CS[k * SR + c4]) =
                *reinterpret_cast<const float4*>(&g_C2[k * KFOLD + nc + c4]);
        }
        __syncthreads();
        u64 accp[4][2];
        #pragma unroll
        for (int j = 0; j < 4; j++) { accp[j][0] = 0; accp[j][1] = 0; }
        #pragma unroll 4
        for (int k = 0; k < NF; k++) {
            float4 av = *reinterpret_cast<const float4*>(&ZS[k * SR + r4]);
            ulonglong2 bq = *reinterpret_cast<const ulonglong2*>(&CS[k * SR + tc * 4]);
            float a[4] = {av.x, av.y, av.z, av.w};
            #pragma unroll
            for (int j = 0; j < 4; j++) {
                u64 a2 = bcast2(a[j]);
                ffma2(accp[j][0], a2, bq.x);
                ffma2(accp[j][1], a2, bq.y);
            }
        }
        float* af = reinterpret_cast<float*>(accp);    // af[j*4 + l]
        int c = nc + tc * 4;
        float sgn = (c < 192) ? 1.f : -1.f;
        #pragma unroll
        for (int j = 0; j < 4; j++) {
            size_t base = (size_t)(row0 + r4 + j) * IN_DIM;
            float4 v = make_float4(sgn * af[j * 4 + 0], sgn * af[j * 4 + 1],
                                   sgn * af[j * 4 + 2], sgn * af[j * 4 + 3]);
            *reinterpret_cast<float4*>(&out[base + c]) = v;
            *reinterpret_cast<float4*>(&out[base + c + 384]) =
                make_float4(-v.x, -v.y, -v.z, -v.w);
        }
    }
}

extern "C" void kernel_launch(void* const* d_in, const int* in_sizes, int n_in,
                              void* d_out, int out_size) {
    const float* x       = (const float*)d_in[0];
    const float* eps     = (const float*)d_in[1];
    const int*   indices = (const int*)  d_in[2];
    const float* mu_w1   = (const float*)d_in[3];
    const float* mu_b1   = (const float*)d_in[4];
    const float* mu_g    = (const float*)d_in[5];
    const float* mu_beta = (const float*)d_in[6];
    const float* mu_w2   = (const float*)d_in[7];
    const float* mu_b2   = (const float*)d_in[8];
    const float* sg_w1   = (const float*)d_in[9];
    const float* sg_b1   = (const float*)d_in[10];
    const float* sg_g    = (const float*)d_in[11];
    const float* sg_beta = (const float*)d_in[12];
    const float* sg_w2   = (const float*)d_in[13];
    const float* sg_b2   = (const float*)d_in[14];
    float* out = (float*)d_out;

    int n_rows = in_sizes[0] / IN_DIM;   // 32768
    int grid = n_rows / ROWS;            // 512

    cudaFuncSetAttribute(k2_mlp,
                         cudaFuncAttributeMaxDynamicSharedMemorySize, K2_SMEM_BYTES);

    int pre_total = KFOLD * NFP + NF * KFOLD + 2 * NF * HID + 2 * HID * NFP;
    precompute_all<<<(pre_total + 255) / 256, 256>>>(indices, mu_w1, sg_w1, mu_w2, sg_w2);

    k1_dft<<<grid, 256>>>(x);
    k2_mlp<<<grid, 512, K2_SMEM_BYTES>>>(eps,
        mu_b1, mu_g, mu_beta, mu_b2,
        sg_b1, sg_g, sg_beta, sg_b2);
    k3_synth<<<grid, 256>>>(out);
}